// round 5
// baseline (speedup 1.0000x reference)
#include <cuda_runtime.h>
#include <math.h>

#define B_ 4
#define C_ 64
#define H_ 128
#define W_ 128
#define O_ 64
#define HW_ (H_*W_)

// Scratch (static device globals -- allocation is forbidden)
__device__ float g_offs[(size_t)B_ * 18 * HW_];   // 18 offset channels per batch
__device__ float g_modmean[(size_t)B_ * HW_];     // mean of 9 sigmoids
__device__ float g_wT[9 * 64 * 64];               // weight transposed [k][c][o]

// ---- packed f32x2 helpers (sm_103a) ---------------------------------------
__device__ __forceinline__ unsigned long long pk2(float lo, float hi) {
    unsigned long long r;
    asm("mov.b64 %0, {%1, %2};" : "=l"(r) : "f"(lo), "f"(hi));
    return r;
}
__device__ __forceinline__ void upk2(unsigned long long v, float& lo, float& hi) {
    asm("mov.b64 {%0, %1}, %2;" : "=f"(lo), "=f"(hi) : "l"(v));
}
__device__ __forceinline__ void fma2(unsigned long long& d,
                                     unsigned long long a,
                                     unsigned long long b) {
    asm("fma.rn.f32x2 %0, %1, %2, %3;" : "=l"(d) : "l"(a), "l"(b), "l"(d));
}

// ---------------------------------------------------------------------------
// Prep: transpose weight [O][C][9] -> g_wT[k][c][o] for coalesced staging.
// ---------------------------------------------------------------------------
__global__ void k_wprep(const float* __restrict__ weight)
{
    int i = blockIdx.x * 256 + threadIdx.x;     // i = (k*64+c)*64+o
    if (i >= 9 * 64 * 64) return;
    int o = i & 63;
    int kc = i >> 6;
    int c = kc & 63;
    int k = kc >> 6;
    g_wT[i] = weight[((size_t)o * 64 + c) * 9 + k];
}

// ---------------------------------------------------------------------------
// Kernel 1: fused offset-conv (18ch) + modulation-conv (9ch) + sigmoid-mean.
// c processed in two halves of 32 so smem = 72KB -> 2 blocks/SM.
// Inner loop uses packed fma.rn.f32x2 (14 FFMA2 per (c,kk)).
// ---------------------------------------------------------------------------
__global__ __launch_bounds__(256, 2) void k_offmod(
    const float* __restrict__ x,
    const float* __restrict__ ow, const float* __restrict__ ob,
    const float* __restrict__ mw, const float* __restrict__ mb)
{
    extern __shared__ float sm1[];
    float* xs = sm1;                  // [32][18][18] : c_local*324 + y*18 + x
    float* wt = sm1 + 32 * 324;       // [(c_local*9+kk)][28] j-contiguous

    const int tid = threadIdx.x;
    const int tx = tid & 15, ty = tid >> 4;
    const int w0 = blockIdx.x * 16, h0 = blockIdx.y * 16;
    const int b = blockIdx.z;
    const float* xb = x + (size_t)b * C_ * HW_;

    unsigned long long acc2[14];
#pragma unroll
    for (int q = 0; q < 14; ++q) acc2[q] = 0ull;

    for (int half = 0; half < 2; ++half) {
        __syncthreads();
        // x tile chunk (32 channels); conv uses zero padding -> zero OOB
        for (int i = tid; i < 32 * 324; i += 256) {
            int c = i / 324, r = i % 324;
            int yy = r / 18, xx = r % 18;
            int gy = h0 + yy - 1, gx = w0 + xx - 1;
            float v = 0.f;
            if (gy >= 0 && gy < H_ && gx >= 0 && gx < W_)
                v = xb[(size_t)(half * 32 + c) * HW_ + gy * W_ + gx];
            xs[i] = v;
        }
        // weight chunk: wt[(c_local*9+kk)*28 + j]
        // j in [0,18): offset weights; [18,27): modulation weights; j=27 pad
        for (int i = tid; i < 32 * 9 * 28; i += 256) {
            int j = i % 28;
            int ckl = i / 28;                 // c_local*9+kk in [0,288)
            int ck = half * 288 + ckl;        // global c*9+kk
            float v = 0.f;
            if (j < 18)       v = ow[(size_t)j * 576 + ck];
            else if (j < 27)  v = mw[(size_t)(j - 18) * 576 + ck];
            wt[i] = v;
        }
        __syncthreads();

        for (int c = 0; c < 32; ++c) {
#pragma unroll
            for (int kk = 0; kk < 9; ++kk) {
                const int ky = kk / 3, kx = kk % 3;
                const float xv = xs[c * 324 + (ty + ky) * 18 + (tx + kx)];
                const unsigned long long xv2 = pk2(xv, xv);
                const ulonglong2* wr =
                    reinterpret_cast<const ulonglong2*>(wt + (c * 9 + kk) * 28);
#pragma unroll
                for (int p = 0; p < 7; ++p) {
                    ulonglong2 wp = wr[p];
                    fma2(acc2[2 * p + 0], xv2, wp.x);
                    fma2(acc2[2 * p + 1], xv2, wp.y);
                }
            }
        }
    }

    const int h = h0 + ty, w = w0 + tx;
    const int hw = h * W_ + w;
    float accs[28];
#pragma unroll
    for (int q = 0; q < 14; ++q) upk2(acc2[q], accs[2 * q], accs[2 * q + 1]);

#pragma unroll
    for (int j = 0; j < 18; ++j)
        g_offs[((size_t)b * 18 + j) * HW_ + hw] = accs[j] + __ldg(&ob[j]);

    float s = 0.f;
#pragma unroll
    for (int j = 0; j < 9; ++j) {
        float z = accs[18 + j] + __ldg(&mb[j]);
        s += 1.f / (1.f + __expf(-z));
    }
    g_modmean[(size_t)b * HW_ + hw] = s * (1.f / 9.f);
}

// ---------------------------------------------------------------------------
// Kernel 2: deformable gather + per-pixel GEMV, restructured.
// Block = 256 threads = 64 pixel-quads x 4 output-chunks(16 o each).
// x tile (64c x 20x20, covers |off|<=~0.5 for all 9 taps) staged once in
// smem; gathers become LDS. Rare out-of-tile warps take a global fallback.
// Weights staged per-k from pre-transposed g_wT; accumulation in fma.rn.f32x2.
// ---------------------------------------------------------------------------
#define RS_ 20
#define PS_ 400
__global__ __launch_bounds__(256, 1) void k_main(
    const float* __restrict__ x,
    const float* __restrict__ bias,
    float* __restrict__ out)
{
    extern __shared__ float sm2[];
    float* xs = sm2;                   // [64][20][20]
    float* wk = sm2 + 64 * PS_;        // [c][o] for current k

    const int tid = threadIdx.x;
    const int og = tid & 3;            // o chunk: o0 = og*16
    const int pg = tid >> 2;           // pixel quad index 0..63
    const int o0 = og * 16;
    const int prow = pg >> 2;          // tile row 0..15
    const int pcol0 = (pg & 3) * 4;    // tile col base (4 consecutive)
    const int b = blockIdx.z;
    const int w0 = blockIdx.x * 16, h0 = blockIdx.y * 16;
    const int h = h0 + prow;
    const int wbase = w0 + pcol0;
    const int hw0 = h * W_ + wbase;    // 4 consecutive output pixels
    const float* xb = x + (size_t)b * C_ * HW_;

    // stage x tile: rows [h0-2, h0+18), cols [w0-2, w0+18), clamped.
    // Clamping is safe: every OOB corner is zero-masked via msk below.
    for (int i = tid; i < 64 * PS_; i += 256) {
        int c = i / PS_, r = i % PS_;
        int yy = r / RS_, xx = r % RS_;
        int gy = min(max(h0 - 2 + yy, 0), H_ - 1);
        int gx = min(max(w0 - 2 + xx, 0), W_ - 1);
        xs[i] = xb[(size_t)c * HW_ + gy * W_ + gx];
    }

    unsigned long long acc2[4][8];
#pragma unroll
    for (int i = 0; i < 4; ++i)
#pragma unroll
        for (int q = 0; q < 8; ++q) acc2[i][q] = 0ull;

    for (int k = 0; k < 9; ++k) {
        __syncthreads();
        // stage weights for this k: wk[c][o] <- g_wT[k][c][o] (coalesced)
        {
            const float4* src = reinterpret_cast<const float4*>(g_wT + k * 4096);
            float4* dst = reinterpret_cast<float4*>(wk);
            for (int i = tid; i < 1024; i += 256) dst[i] = src[i];
        }
        __syncthreads();

        const int ky = k / 3 - 1, kx = k % 3 - 1;

        int   loff[4][4];    // local smem offsets per px per corner
        float msk[4][4];     // bilinear weights (zero-masked at image border)
        int   gy0[4], gx0[4];
        bool fast = true;
#pragma unroll
        for (int i = 0; i < 4; ++i) {
            const int hw = hw0 + i;
            const float sy = (float)(h + ky)
                + g_offs[((size_t)b * 18 + k) * HW_ + hw];
            const float sx = (float)(wbase + i + kx)
                + g_offs[((size_t)b * 18 + 9 + k) * HW_ + hw];
            const float y0f = floorf(sy), x0f = floorf(sx);
            const float wy1 = sy - y0f, wx1 = sx - x0f;
            const float wy0 = 1.f - wy1, wx0 = 1.f - wx1;
            const int y0 = (int)y0f, x0 = (int)x0f;
            gy0[i] = y0; gx0[i] = x0;
            const bool vy0 = (y0 >= 0) & (y0 < H_);
            const bool vy1 = (y0 + 1 >= 0) & (y0 + 1 < H_);
            const bool vx0 = (x0 >= 0) & (x0 < W_);
            const bool vx1 = (x0 + 1 >= 0) & (x0 + 1 < W_);
            msk[i][0] = (vy0 && vx0) ? wy0 * wx0 : 0.f;
            msk[i][1] = (vy0 && vx1) ? wy0 * wx1 : 0.f;
            msk[i][2] = (vy1 && vx0) ? wy1 * wx0 : 0.f;
            msk[i][3] = (vy1 && vx1) ? wy1 * wx1 : 0.f;
            const int ly = y0 - (h0 - 2), lx = x0 - (w0 - 2);
            const int l0 = ly * RS_ + lx;
            loff[i][0] = l0;           loff[i][1] = l0 + 1;
            loff[i][2] = l0 + RS_;     loff[i][3] = l0 + RS_ + 1;
            fast &= (y0 >= h0 - 2) & (y0 <= h0 + 16)
                  & (x0 >= w0 - 2) & (x0 <= w0 + 16);
        }

        if (__all_sync(0xffffffffu, fast)) {
            // fast path: all gathers from smem tile
            for (int c = 0; c < 64; ++c) {
                const float* xc = xs + c * PS_;
                const ulonglong2* wrow =
                    reinterpret_cast<const ulonglong2*>(wk + c * 64 + o0);
                ulonglong2 wA = wrow[0], wB = wrow[1], wC = wrow[2], wD = wrow[3];
#pragma unroll
                for (int i = 0; i < 4; ++i) {
                    float v = msk[i][0] * xc[loff[i][0]]
                            + msk[i][1] * xc[loff[i][1]]
                            + msk[i][2] * xc[loff[i][2]]
                            + msk[i][3] * xc[loff[i][3]];
                    const unsigned long long vv = pk2(v, v);
                    fma2(acc2[i][0], vv, wA.x); fma2(acc2[i][1], vv, wA.y);
                    fma2(acc2[i][2], vv, wB.x); fma2(acc2[i][3], vv, wB.y);
                    fma2(acc2[i][4], vv, wC.x); fma2(acc2[i][5], vv, wC.y);
                    fma2(acc2[i][6], vv, wD.x); fma2(acc2[i][7], vv, wD.y);
                }
            }
        } else {
            // slow path (rare): gathers from global with clamped indices
            int gidx[4][4];
#pragma unroll
            for (int i = 0; i < 4; ++i) {
                const int cy0 = min(max(gy0[i], 0), H_ - 1);
                const int cy1 = min(max(gy0[i] + 1, 0), H_ - 1);
                const int cx0 = min(max(gx0[i], 0), W_ - 1);
                const int cx1 = min(max(gx0[i] + 1, 0), W_ - 1);
                gidx[i][0] = cy0 * W_ + cx0; gidx[i][1] = cy0 * W_ + cx1;
                gidx[i][2] = cy1 * W_ + cx0; gidx[i][3] = cy1 * W_ + cx1;
            }
            for (int c = 0; c < 64; ++c) {
                const float* xc = xb + (size_t)c * HW_;
                const ulonglong2* wrow =
                    reinterpret_cast<const ulonglong2*>(wk + c * 64 + o0);
                ulonglong2 wA = wrow[0], wB = wrow[1], wC = wrow[2], wD = wrow[3];
#pragma unroll
                for (int i = 0; i < 4; ++i) {
                    float v = msk[i][0] * __ldg(xc + gidx[i][0])
                            + msk[i][1] * __ldg(xc + gidx[i][1])
                            + msk[i][2] * __ldg(xc + gidx[i][2])
                            + msk[i][3] * __ldg(xc + gidx[i][3]);
                    const unsigned long long vv = pk2(v, v);
                    fma2(acc2[i][0], vv, wA.x); fma2(acc2[i][1], vv, wA.y);
                    fma2(acc2[i][2], vv, wB.x); fma2(acc2[i][3], vv, wB.y);
                    fma2(acc2[i][4], vv, wC.x); fma2(acc2[i][5], vv, wC.y);
                    fma2(acc2[i][6], vv, wD.x); fma2(acc2[i][7], vv, wD.y);
                }
            }
        }
    }

    // epilogue: out[b][o][hw0..hw0+3] as float4 stores
    float mm[4];
#pragma unroll
    for (int i = 0; i < 4; ++i) mm[i] = g_modmean[(size_t)b * HW_ + hw0 + i];

#pragma unroll
    for (int q = 0; q < 8; ++q) {
        float a0[4], a1[4];
#pragma unroll
        for (int i = 0; i < 4; ++i) upk2(acc2[i][q], a0[i], a1[i]);
        const int oa = o0 + 2 * q, ob2 = oa + 1;
        const float ba = __ldg(&bias[oa]), bb = __ldg(&bias[ob2]);
        float4 va, vb;
        va.x = fmaf(a0[0], mm[0], ba); va.y = fmaf(a0[1], mm[1], ba);
        va.z = fmaf(a0[2], mm[2], ba); va.w = fmaf(a0[3], mm[3], ba);
        vb.x = fmaf(a1[0], mm[0], bb); vb.y = fmaf(a1[1], mm[1], bb);
        vb.z = fmaf(a1[2], mm[2], bb); vb.w = fmaf(a1[3], mm[3], bb);
        *reinterpret_cast<float4*>(out + ((size_t)b * 64 + oa) * HW_ + hw0) = va;
        *reinterpret_cast<float4*>(out + ((size_t)b * 64 + ob2) * HW_ + hw0) = vb;
    }
}

// ---------------------------------------------------------------------------
extern "C" void kernel_launch(void* const* d_in, const int* in_sizes, int n_in,
                              void* d_out, int out_size)
{
    const float* x      = (const float*)d_in[0];
    const float* weight = (const float*)d_in[1];
    const float* bias   = (const float*)d_in[2];
    const float* ow     = (const float*)d_in[3];
    const float* ob     = (const float*)d_in[4];
    const float* mw     = (const float*)d_in[5];
    const float* mb     = (const float*)d_in[6];
    float* out = (float*)d_out;

    const size_t sm_off  = (size_t)(32 * 324 + 32 * 9 * 28) * sizeof(float); // 73728
    const size_t sm_main = (size_t)(64 * PS_ + 64 * 64) * sizeof(float);     // 118784
    cudaFuncSetAttribute(k_offmod, cudaFuncAttributeMaxDynamicSharedMemorySize,
                         (int)sm_off);
    cudaFuncSetAttribute(k_main, cudaFuncAttributeMaxDynamicSharedMemorySize,
                         (int)sm_main);

    dim3 grd(W_ / 16, H_ / 16, B_);
    k_wprep<<<(9 * 64 * 64 + 255) / 256, 256>>>(weight);
    k_offmod<<<grd, 256, sm_off>>>(x, ow, ob, mw, mb);
    k_main<<<grd, 256, sm_main>>>(x, bias, out);
}

// round 6
// speedup vs baseline: 1.6189x; 1.6189x over previous
#include <cuda_runtime.h>
#include <math.h>

#define B_ 4
#define C_ 64
#define H_ 128
#define W_ 128
#define O_ 64
#define HW_ (H_*W_)

// Scratch (static device globals -- allocation is forbidden)
__device__ float g_offs[(size_t)B_ * 18 * HW_];   // 18 offset channels per batch
__device__ float g_modmean[(size_t)B_ * HW_];     // mean of 9 sigmoids
__device__ float g_wT[9 * 64 * 64];               // weight, swizzled per-k (see k_wprep)

// ---- packed f32x2 helpers (sm_103a) ---------------------------------------
__device__ __forceinline__ unsigned long long pk2(float lo, float hi) {
    unsigned long long r;
    asm("mov.b64 %0, {%1, %2};" : "=l"(r) : "f"(lo), "f"(hi));
    return r;
}
__device__ __forceinline__ void upk2(unsigned long long v, float& lo, float& hi) {
    asm("mov.b64 {%0, %1}, %2;" : "=f"(lo), "=f"(hi) : "l"(v));
}
__device__ __forceinline__ void fma2(unsigned long long& d,
                                     unsigned long long a,
                                     unsigned long long b) {
    asm("fma.rn.f32x2 %0, %1, %2, %3;" : "=l"(d) : "l"(a), "l"(b), "l"(d));
}

// ---------------------------------------------------------------------------
// Prep: weight [O][C][9] -> g_wT[k][c][j] where j = q*16 + og*4 + e encodes
// o = og*16 + q*4 + e. This interleaving makes the 4 og-chunk LDS.128 reads
// in k_main phase B hit distinct banks (no 64B-span mod-128B collisions).
// ---------------------------------------------------------------------------
__global__ void k_wprep(const float* __restrict__ weight)
{
    int i = blockIdx.x * 256 + threadIdx.x;     // i = (k*64+c)*64 + j
    if (i >= 9 * 64 * 64) return;
    int j = i & 63;
    int kc = i >> 6;
    int c = kc & 63;
    int k = kc >> 6;
    int q  = j >> 4;
    int og = (j >> 2) & 3;
    int e  = j & 3;
    int o  = og * 16 + q * 4 + e;
    g_wT[i] = weight[((size_t)o * 64 + c) * 9 + k];
}

// ---------------------------------------------------------------------------
// Kernel 1: fused offset-conv (18ch) + modulation-conv (9ch) + sigmoid-mean.
// c processed in two halves of 32 so smem = 72KB -> 2 blocks/SM.
// Inner loop uses packed fma.rn.f32x2 (14 FFMA2 per (c,kk)).
// ---------------------------------------------------------------------------
__global__ __launch_bounds__(256, 2) void k_offmod(
    const float* __restrict__ x,
    const float* __restrict__ ow, const float* __restrict__ ob,
    const float* __restrict__ mw, const float* __restrict__ mb)
{
    extern __shared__ float sm1[];
    float* xs = sm1;                  // [32][18][18] : c_local*324 + y*18 + x
    float* wt = sm1 + 32 * 324;       // [(c_local*9+kk)][28] j-contiguous

    const int tid = threadIdx.x;
    const int tx = tid & 15, ty = tid >> 4;
    const int w0 = blockIdx.x * 16, h0 = blockIdx.y * 16;
    const int b = blockIdx.z;
    const float* xb = x + (size_t)b * C_ * HW_;

    unsigned long long acc2[14];
#pragma unroll
    for (int q = 0; q < 14; ++q) acc2[q] = 0ull;

    for (int half = 0; half < 2; ++half) {
        __syncthreads();
        // x tile chunk (32 channels); conv uses zero padding -> zero OOB
        for (int i = tid; i < 32 * 324; i += 256) {
            int c = i / 324, r = i % 324;
            int yy = r / 18, xx = r % 18;
            int gy = h0 + yy - 1, gx = w0 + xx - 1;
            float v = 0.f;
            if (gy >= 0 && gy < H_ && gx >= 0 && gx < W_)
                v = xb[(size_t)(half * 32 + c) * HW_ + gy * W_ + gx];
            xs[i] = v;
        }
        // weight chunk: wt[(c_local*9+kk)*28 + j]
        for (int i = tid; i < 32 * 9 * 28; i += 256) {
            int j = i % 28;
            int ckl = i / 28;                 // c_local*9+kk in [0,288)
            int ck = half * 288 + ckl;        // global c*9+kk
            float v = 0.f;
            if (j < 18)       v = ow[(size_t)j * 576 + ck];
            else if (j < 27)  v = mw[(size_t)(j - 18) * 576 + ck];
            wt[i] = v;
        }
        __syncthreads();

        for (int c = 0; c < 32; ++c) {
#pragma unroll
            for (int kk = 0; kk < 9; ++kk) {
                const int ky = kk / 3, kx = kk % 3;
                const float xv = xs[c * 324 + (ty + ky) * 18 + (tx + kx)];
                const unsigned long long xv2 = pk2(xv, xv);
                const ulonglong2* wr =
                    reinterpret_cast<const ulonglong2*>(wt + (c * 9 + kk) * 28);
#pragma unroll
                for (int p = 0; p < 7; ++p) {
                    ulonglong2 wp = wr[p];
                    fma2(acc2[2 * p + 0], xv2, wp.x);
                    fma2(acc2[2 * p + 1], xv2, wp.y);
                }
            }
        }
    }

    const int h = h0 + ty, w = w0 + tx;
    const int hw = h * W_ + w;
    float accs[28];
#pragma unroll
    for (int q = 0; q < 14; ++q) upk2(acc2[q], accs[2 * q], accs[2 * q + 1]);

#pragma unroll
    for (int j = 0; j < 18; ++j)
        g_offs[((size_t)b * 18 + j) * HW_ + hw] = accs[j] + __ldg(&ob[j]);

    float s = 0.f;
#pragma unroll
    for (int j = 0; j < 9; ++j) {
        float z = accs[18 + j] + __ldg(&mb[j]);
        s += 1.f / (1.f + __expf(-z));
    }
    g_modmean[(size_t)b * HW_ + hw] = s * (1.f / 9.f);
}

// ---------------------------------------------------------------------------
// Kernel 2 (v3): per k-tap, two phases inside the block.
//  Phase A: thread = 1 pixel. Bilinear params once, then 64 channels of v
//           via 4 clamped+masked __ldg each -> smem S[c][256] (exact for any
//           offset; no tile, no fallback path).
//  Phase B: thread = 4 px x 16 o. Per c: 1 LDS.128 of S (conflict-free) +
//           4 conflict-free W LDS.128 (swizzled layout) + 32 FFMA2.
// smem = 80KB -> 2 blocks/SM (16 warps).
// ---------------------------------------------------------------------------
__global__ __launch_bounds__(256, 2) void k_main(
    const float* __restrict__ x,
    const float* __restrict__ bias,
    float* __restrict__ out)
{
    extern __shared__ float sm2[];
    float* S  = sm2;                   // [64 c][256 px]
    float* wk = sm2 + 64 * 256;        // [c][64] swizzled (q*16 + og*4 + e)

    const int tid = threadIdx.x;
    // phase A identity: one pixel
    const int arow = tid >> 4, acol = tid & 15;
    // phase B identity: quad of pixels x 16 outputs
    const int og = tid & 3;
    const int pg = tid >> 2;
    const int px0 = pg * 4;
    const int brow = px0 >> 4, bcol = px0 & 15;

    const int b = blockIdx.z;
    const int w0 = blockIdx.x * 16, h0 = blockIdx.y * 16;
    const float* xb = x + (size_t)b * C_ * HW_;

    const int ah = h0 + arow, aw = w0 + acol;
    const int ahw = ah * W_ + aw;
    const int bh = h0 + brow, bw = w0 + bcol;
    const int bhw0 = bh * W_ + bw;     // 4 consecutive output pixels

    unsigned long long acc2[4][8];     // [px][2*q+p] <-> o = og*16 + 4q + 2p
#pragma unroll
    for (int i = 0; i < 4; ++i)
#pragma unroll
        for (int q = 0; q < 8; ++q) acc2[i][q] = 0ull;

    for (int k = 0; k < 9; ++k) {
        __syncthreads();   // S / wk from previous iteration fully consumed

        // ---- stage weights for this k (already swizzled in g_wT) ----
        {
            const float4* src = reinterpret_cast<const float4*>(g_wT + k * 4096);
            float4* dst = reinterpret_cast<float4*>(wk);
#pragma unroll
            for (int i = 0; i < 4; ++i) dst[tid + 256 * i] = src[tid + 256 * i];
        }

        // ---- Phase A: gather 64 channels for this thread's pixel ----
        {
            const int ky = k / 3 - 1, kx = k % 3 - 1;
            const float sy = (float)(ah + ky)
                + g_offs[((size_t)b * 18 + k) * HW_ + ahw];
            const float sx = (float)(aw + kx)
                + g_offs[((size_t)b * 18 + 9 + k) * HW_ + ahw];
            const float y0f = floorf(sy), x0f = floorf(sx);
            const float wy1 = sy - y0f, wx1 = sx - x0f;
            const float wy0 = 1.f - wy1, wx0 = 1.f - wx1;
            const int y0 = (int)y0f, x0 = (int)x0f;
            const bool vy0 = (y0 >= 0) & (y0 < H_);
            const bool vy1 = (y0 + 1 >= 0) & (y0 + 1 < H_);
            const bool vx0 = (x0 >= 0) & (x0 < W_);
            const bool vx1 = (x0 + 1 >= 0) & (x0 + 1 < W_);
            const float m00 = (vy0 && vx0) ? wy0 * wx0 : 0.f;
            const float m01 = (vy0 && vx1) ? wy0 * wx1 : 0.f;
            const float m10 = (vy1 && vx0) ? wy1 * wx0 : 0.f;
            const float m11 = (vy1 && vx1) ? wy1 * wx1 : 0.f;
            const int cy0 = min(max(y0, 0), H_ - 1);
            const int cy1 = min(max(y0 + 1, 0), H_ - 1);
            const int cx0 = min(max(x0, 0), W_ - 1);
            const int cx1 = min(max(x0 + 1, 0), W_ - 1);
            const int i00 = cy0 * W_ + cx0, i01 = cy0 * W_ + cx1;
            const int i10 = cy1 * W_ + cx0, i11 = cy1 * W_ + cx1;

            const float* xc = xb;
            float* Sp = S + tid;
#pragma unroll 8
            for (int c = 0; c < 64; ++c) {
                float v = m00 * __ldg(xc + i00) + m01 * __ldg(xc + i01)
                        + m10 * __ldg(xc + i10) + m11 * __ldg(xc + i11);
                Sp[c * 256] = v;
                xc += HW_;
            }
        }
        __syncthreads();

        // ---- Phase B: GEMM S^T x W ----
        {
            const float* Sp = S + px0;
            const float* wp = wk + og * 4;
            for (int c = 0; c < 64; ++c) {
                const float4 sv = *reinterpret_cast<const float4*>(Sp + c * 256);
                const float* wc = wp + c * 64;
                const ulonglong2 wA = *reinterpret_cast<const ulonglong2*>(wc);
                const ulonglong2 wB = *reinterpret_cast<const ulonglong2*>(wc + 16);
                const ulonglong2 wC = *reinterpret_cast<const ulonglong2*>(wc + 32);
                const ulonglong2 wD = *reinterpret_cast<const ulonglong2*>(wc + 48);
                const unsigned long long v0 = pk2(sv.x, sv.x);
                const unsigned long long v1 = pk2(sv.y, sv.y);
                const unsigned long long v2 = pk2(sv.z, sv.z);
                const unsigned long long v3 = pk2(sv.w, sv.w);
                fma2(acc2[0][0], v0, wA.x); fma2(acc2[0][1], v0, wA.y);
                fma2(acc2[0][2], v0, wB.x); fma2(acc2[0][3], v0, wB.y);
                fma2(acc2[0][4], v0, wC.x); fma2(acc2[0][5], v0, wC.y);
                fma2(acc2[0][6], v0, wD.x); fma2(acc2[0][7], v0, wD.y);
                fma2(acc2[1][0], v1, wA.x); fma2(acc2[1][1], v1, wA.y);
                fma2(acc2[1][2], v1, wB.x); fma2(acc2[1][3], v1, wB.y);
                fma2(acc2[1][4], v1, wC.x); fma2(acc2[1][5], v1, wC.y);
                fma2(acc2[1][6], v1, wD.x); fma2(acc2[1][7], v1, wD.y);
                fma2(acc2[2][0], v2, wA.x); fma2(acc2[2][1], v2, wA.y);
                fma2(acc2[2][2], v2, wB.x); fma2(acc2[2][3], v2, wB.y);
                fma2(acc2[2][4], v2, wC.x); fma2(acc2[2][5], v2, wC.y);
                fma2(acc2[2][6], v2, wD.x); fma2(acc2[2][7], v2, wD.y);
                fma2(acc2[3][0], v3, wA.x); fma2(acc2[3][1], v3, wA.y);
                fma2(acc2[3][2], v3, wB.x); fma2(acc2[3][3], v3, wB.y);
                fma2(acc2[3][4], v3, wC.x); fma2(acc2[3][5], v3, wC.y);
                fma2(acc2[3][6], v3, wD.x); fma2(acc2[3][7], v3, wD.y);
            }
        }
    }

    // epilogue: acc2[i][2q+p] holds o = og*16 + 4q + 2p (+1 in hi half)
    float mm[4];
#pragma unroll
    for (int i = 0; i < 4; ++i) mm[i] = g_modmean[(size_t)b * HW_ + bhw0 + i];

#pragma unroll
    for (int q = 0; q < 4; ++q) {
#pragma unroll
        for (int p = 0; p < 2; ++p) {
            float a0[4], a1[4];
#pragma unroll
            for (int i = 0; i < 4; ++i) upk2(acc2[i][2 * q + p], a0[i], a1[i]);
            const int oa = og * 16 + 4 * q + 2 * p, ob2 = oa + 1;
            const float ba = __ldg(&bias[oa]), bb = __ldg(&bias[ob2]);
            float4 va, vb;
            va.x = fmaf(a0[0], mm[0], ba); va.y = fmaf(a0[1], mm[1], ba);
            va.z = fmaf(a0[2], mm[2], ba); va.w = fmaf(a0[3], mm[3], ba);
            vb.x = fmaf(a1[0], mm[0], bb); vb.y = fmaf(a1[1], mm[1], bb);
            vb.z = fmaf(a1[2], mm[2], bb); vb.w = fmaf(a1[3], mm[3], bb);
            *reinterpret_cast<float4*>(out + ((size_t)b * 64 + oa) * HW_ + bhw0) = va;
            *reinterpret_cast<float4*>(out + ((size_t)b * 64 + ob2) * HW_ + bhw0) = vb;
        }
    }
}

// ---------------------------------------------------------------------------
extern "C" void kernel_launch(void* const* d_in, const int* in_sizes, int n_in,
                              void* d_out, int out_size)
{
    const float* x      = (const float*)d_in[0];
    const float* weight = (const float*)d_in[1];
    const float* bias   = (const float*)d_in[2];
    const float* ow     = (const float*)d_in[3];
    const float* ob     = (const float*)d_in[4];
    const float* mw     = (const float*)d_in[5];
    const float* mb     = (const float*)d_in[6];
    float* out = (float*)d_out;

    const size_t sm_off  = (size_t)(32 * 324 + 32 * 9 * 28) * sizeof(float); // 73728
    const size_t sm_main = (size_t)(64 * 256 + 64 * 64) * sizeof(float);     // 81920
    cudaFuncSetAttribute(k_offmod, cudaFuncAttributeMaxDynamicSharedMemorySize,
                         (int)sm_off);
    cudaFuncSetAttribute(k_main, cudaFuncAttributeMaxDynamicSharedMemorySize,
                         (int)sm_main);

    dim3 grd(W_ / 16, H_ / 16, B_);
    k_wprep<<<(9 * 64 * 64 + 255) / 256, 256>>>(weight);
    k_offmod<<<grd, 256, sm_off>>>(x, ow, ob, mw, mb);
    k_main<<<grd, 256, sm_main>>>(x, bias, out);
}

// round 8
// speedup vs baseline: 1.6995x; 1.0498x over previous
#include <cuda_runtime.h>
#include <math.h>

#define B_ 4
#define C_ 64
#define H_ 128
#define W_ 128
#define O_ 64
#define HW_ (H_*W_)

// Scratch (static device globals -- allocation is forbidden)
__device__ float g_offs[(size_t)B_ * 18 * HW_];   // 18 offset channels per batch
__device__ float g_modmean[(size_t)B_ * HW_];     // mean of 9 sigmoids
__device__ float g_wT[9 * 64 * 64];               // weight, swizzled per-k (see k_wprep)

// ---- packed f32x2 helpers (sm_103a) ---------------------------------------
__device__ __forceinline__ unsigned long long pk2(float lo, float hi) {
    unsigned long long r;
    asm("mov.b64 %0, {%1, %2};" : "=l"(r) : "f"(lo), "f"(hi));
    return r;
}
__device__ __forceinline__ void upk2(unsigned long long v, float& lo, float& hi) {
    asm("mov.b64 {%0, %1}, %2;" : "=f"(lo), "=f"(hi) : "l"(v));
}
__device__ __forceinline__ void fma2(unsigned long long& d,
                                     unsigned long long a,
                                     unsigned long long b) {
    asm("fma.rn.f32x2 %0, %1, %2, %3;" : "=l"(d) : "l"(a), "l"(b), "l"(d));
}

// ---------------------------------------------------------------------------
// Prep: weight [O][C][9] -> g_wT[k][c][j] where j = q*16 + og*4 + e encodes
// o = og*16 + q*4 + e. The interleaving makes the 4 og-chunk LDS.128 reads
// in k_main conflict-free across lanes.
// ---------------------------------------------------------------------------
__global__ void k_wprep(const float* __restrict__ weight)
{
    int i = blockIdx.x * 256 + threadIdx.x;     // i = (k*64+c)*64 + j
    if (i >= 9 * 64 * 64) return;
    int j = i & 63;
    int kc = i >> 6;
    int c = kc & 63;
    int k = kc >> 6;
    int q  = j >> 4;
    int og = (j >> 2) & 3;
    int e  = j & 3;
    int o  = og * 16 + q * 4 + e;
    g_wT[i] = weight[((size_t)o * 64 + c) * 9 + k];
}

// ---------------------------------------------------------------------------
// Kernel 1: fused offset-conv (18ch) + modulation-conv (9ch) + sigmoid-mean.
// c processed in two halves of 32 so smem = 72KB -> 2 blocks/SM.
// Inner loop uses packed fma.rn.f32x2 (14 FFMA2 per (c,kk)).
// ---------------------------------------------------------------------------
__global__ __launch_bounds__(256, 2) void k_offmod(
    const float* __restrict__ x,
    const float* __restrict__ ow, const float* __restrict__ ob,
    const float* __restrict__ mw, const float* __restrict__ mb)
{
    extern __shared__ float sm1[];
    float* xs = sm1;                  // [32][18][18] : c_local*324 + y*18 + x
    float* wt = sm1 + 32 * 324;       // [(c_local*9+kk)][28] j-contiguous

    const int tid = threadIdx.x;
    const int tx = tid & 15, ty = tid >> 4;
    const int w0 = blockIdx.x * 16, h0 = blockIdx.y * 16;
    const int b = blockIdx.z;
    const float* xb = x + (size_t)b * C_ * HW_;

    unsigned long long acc2[14];
#pragma unroll
    for (int q = 0; q < 14; ++q) acc2[q] = 0ull;

    for (int half = 0; half < 2; ++half) {
        __syncthreads();
        // x tile chunk (32 channels); conv uses zero padding -> zero OOB
        for (int i = tid; i < 32 * 324; i += 256) {
            int c = i / 324, r = i % 324;
            int yy = r / 18, xx = r % 18;
            int gy = h0 + yy - 1, gx = w0 + xx - 1;
            float v = 0.f;
            if (gy >= 0 && gy < H_ && gx >= 0 && gx < W_)
                v = xb[(size_t)(half * 32 + c) * HW_ + gy * W_ + gx];
            xs[i] = v;
        }
        // weight chunk: wt[(c_local*9+kk)*28 + j]
        for (int i = tid; i < 32 * 9 * 28; i += 256) {
            int j = i % 28;
            int ckl = i / 28;                 // c_local*9+kk in [0,288)
            int ck = half * 288 + ckl;        // global c*9+kk
            float v = 0.f;
            if (j < 18)       v = ow[(size_t)j * 576 + ck];
            else if (j < 27)  v = mw[(size_t)(j - 18) * 576 + ck];
            wt[i] = v;
        }
        __syncthreads();

        for (int c = 0; c < 32; ++c) {
#pragma unroll
            for (int kk = 0; kk < 9; ++kk) {
                const int ky = kk / 3, kx = kk % 3;
                const float xv = xs[c * 324 + (ty + ky) * 18 + (tx + kx)];
                const unsigned long long xv2 = pk2(xv, xv);
                const ulonglong2* wr =
                    reinterpret_cast<const ulonglong2*>(wt + (c * 9 + kk) * 28);
#pragma unroll
                for (int p = 0; p < 7; ++p) {
                    ulonglong2 wp = wr[p];
                    fma2(acc2[2 * p + 0], xv2, wp.x);
                    fma2(acc2[2 * p + 1], xv2, wp.y);
                }
            }
        }
    }

    const int h = h0 + ty, w = w0 + tx;
    const int hw = h * W_ + w;
    float accs[28];
#pragma unroll
    for (int q = 0; q < 14; ++q) upk2(acc2[q], accs[2 * q], accs[2 * q + 1]);

#pragma unroll
    for (int j = 0; j < 18; ++j)
        g_offs[((size_t)b * 18 + j) * HW_ + hw] = accs[j] + __ldg(&ob[j]);

    float s = 0.f;
#pragma unroll
    for (int j = 0; j < 9; ++j) {
        float z = accs[18 + j] + __ldg(&mb[j]);
        s += 1.f / (1.f + __expf(-z));
    }
    g_modmean[(size_t)b * HW_ + hw] = s * (1.f / 9.f);
}

// ---------------------------------------------------------------------------
// Kernel 2 (v4): warp-local gather+GEMM, no S array, no phase barriers.
// Block = 32x8 px tile, 8 warps; warp = one image row of 32 px.
// Per c: lane gathers v for its own pixel (4 masked LDG, exact for any
// offset), the 4 lanes of each quad exchange v via shfl, then each lane
// (quad, og) does 32 FFMA2 against its 16-output weight chunk from smem.
// smem = 16KB (weights only), 2 blocks/SM.
// ---------------------------------------------------------------------------
__global__ __launch_bounds__(256, 2) void k_main(
    const float* __restrict__ x,
    const float* __restrict__ bias,
    float* __restrict__ out)
{
    __shared__ float wk[64 * 64];      // [c][j] swizzled (q*16 + og*4 + e)

    const int tid = threadIdx.x;
    const int wid = tid >> 5, lane = tid & 31;
    const int quad = lane >> 2, og = lane & 3;
    const int b = blockIdx.z;
    const int w0 = blockIdx.x * 32, h0 = blockIdx.y * 8;
    const int h = h0 + wid;
    const int aw = w0 + lane;          // gather identity: own pixel
    const int ahw = h * W_ + aw;
    const int bw = w0 + quad * 4;      // GEMM identity: quad of pixels
    const int bhw0 = h * W_ + bw;
    const float* xb = x + (size_t)b * C_ * HW_;

    unsigned long long acc2[4][8];     // [px][2*q+p] <-> o = og*16 + 4q + 2p
#pragma unroll
    for (int i = 0; i < 4; ++i)
#pragma unroll
        for (int q = 0; q < 8; ++q) acc2[i][q] = 0ull;

    for (int k = 0; k < 9; ++k) {
        __syncthreads();               // previous wk fully consumed
        // stage weights for this k (already swizzled in g_wT)
        {
            const float4* src = reinterpret_cast<const float4*>(g_wT + k * 4096);
            float4* dst = reinterpret_cast<float4*>(wk);
#pragma unroll
            for (int i = 0; i < 4; ++i) dst[tid + 256 * i] = src[tid + 256 * i];
        }
        __syncthreads();

        // bilinear setup for this lane's pixel
        const int ky = k / 3 - 1, kx = k % 3 - 1;
        const float sy = (float)(h + ky)
            + g_offs[((size_t)b * 18 + k) * HW_ + ahw];
        const float sx = (float)(aw + kx)
            + g_offs[((size_t)b * 18 + 9 + k) * HW_ + ahw];
        const float y0f = floorf(sy), x0f = floorf(sx);
        const float wy1 = sy - y0f, wx1 = sx - x0f;
        const float wy0 = 1.f - wy1, wx0 = 1.f - wx1;
        const int y0 = (int)y0f, x0 = (int)x0f;
        const bool vy0 = (y0 >= 0) & (y0 < H_);
        const bool vy1 = (y0 + 1 >= 0) & (y0 + 1 < H_);
        const bool vx0 = (x0 >= 0) & (x0 < W_);
        const bool vx1 = (x0 + 1 >= 0) & (x0 + 1 < W_);
        const float m00 = (vy0 && vx0) ? wy0 * wx0 : 0.f;
        const float m01 = (vy0 && vx1) ? wy0 * wx1 : 0.f;
        const float m10 = (vy1 && vx0) ? wy1 * wx0 : 0.f;
        const float m11 = (vy1 && vx1) ? wy1 * wx1 : 0.f;
        const int cy0 = min(max(y0, 0), H_ - 1);
        const int cy1 = min(max(y0 + 1, 0), H_ - 1);
        const int cx0 = min(max(x0, 0), W_ - 1);
        const int cx1 = min(max(x0 + 1, 0), W_ - 1);
        const int i00 = cy0 * W_ + cx0, i01 = cy0 * W_ + cx1;
        const int i10 = cy1 * W_ + cx0, i11 = cy1 * W_ + cx1;
        const int qb = lane & ~3;      // quad base lane

#pragma unroll 4
        for (int c = 0; c < 64; ++c) {
            const float* xc = xb + (size_t)c * HW_;
            const float v = m00 * __ldg(xc + i00) + m01 * __ldg(xc + i01)
                          + m10 * __ldg(xc + i10) + m11 * __ldg(xc + i11);
            // warp-local transpose: broadcast quad's 4 pixel values
            const float v0f = __shfl_sync(0xffffffffu, v, qb + 0);
            const float v1f = __shfl_sync(0xffffffffu, v, qb + 1);
            const float v2f = __shfl_sync(0xffffffffu, v, qb + 2);
            const float v3f = __shfl_sync(0xffffffffu, v, qb + 3);
            const unsigned long long v0 = pk2(v0f, v0f);
            const unsigned long long v1 = pk2(v1f, v1f);
            const unsigned long long v2 = pk2(v2f, v2f);
            const unsigned long long v3 = pk2(v3f, v3f);

            const float* wc = wk + c * 64 + og * 4;
            const ulonglong2 wA = *reinterpret_cast<const ulonglong2*>(wc);
            const ulonglong2 wB = *reinterpret_cast<const ulonglong2*>(wc + 16);
            const ulonglong2 wC = *reinterpret_cast<const ulonglong2*>(wc + 32);
            const ulonglong2 wD = *reinterpret_cast<const ulonglong2*>(wc + 48);

            fma2(acc2[0][0], v0, wA.x); fma2(acc2[0][1], v0, wA.y);
            fma2(acc2[0][2], v0, wB.x); fma2(acc2[0][3], v0, wB.y);
            fma2(acc2[0][4], v0, wC.x); fma2(acc2[0][5], v0, wC.y);
            fma2(acc2[0][6], v0, wD.x); fma2(acc2[0][7], v0, wD.y);
            fma2(acc2[1][0], v1, wA.x); fma2(acc2[1][1], v1, wA.y);
            fma2(acc2[1][2], v1, wB.x); fma2(acc2[1][3], v1, wB.y);
            fma2(acc2[1][4], v1, wC.x); fma2(acc2[1][5], v1, wC.y);
            fma2(acc2[1][6], v1, wD.x); fma2(acc2[1][7], v1, wD.y);
            fma2(acc2[2][0], v2, wA.x); fma2(acc2[2][1], v2, wA.y);
            fma2(acc2[2][2], v2, wB.x); fma2(acc2[2][3], v2, wB.y);
            fma2(acc2[2][4], v2, wC.x); fma2(acc2[2][5], v2, wC.y);
            fma2(acc2[2][6], v2, wD.x); fma2(acc2[2][7], v2, wD.y);
            fma2(acc2[3][0], v3, wA.x); fma2(acc2[3][1], v3, wA.y);
            fma2(acc2[3][2], v3, wB.x); fma2(acc2[3][3], v3, wB.y);
            fma2(acc2[3][4], v3, wC.x); fma2(acc2[3][5], v3, wC.y);
            fma2(acc2[3][6], v3, wD.x); fma2(acc2[3][7], v3, wD.y);
        }
    }

    // epilogue: acc2[i][2q+p] holds o = og*16 + 4q + 2p (+1 in hi half)
    float mm[4];
#pragma unroll
    for (int i = 0; i < 4; ++i) mm[i] = g_modmean[(size_t)b * HW_ + bhw0 + i];

#pragma unroll
    for (int q = 0; q < 4; ++q) {
#pragma unroll
        for (int p = 0; p < 2; ++p) {
            float a0[4], a1[4];
#pragma unroll
            for (int i = 0; i < 4; ++i) upk2(acc2[i][2 * q + p], a0[i], a1[i]);
            const int oa = og * 16 + 4 * q + 2 * p, ob2 = oa + 1;
            const float ba = __ldg(&bias[oa]), bb = __ldg(&bias[ob2]);
            float4 va, vb;
            va.x = fmaf(a0[0], mm[0], ba); va.y = fmaf(a0[1], mm[1], ba);
            va.z = fmaf(a0[2], mm[2], ba); va.w = fmaf(a0[3], mm[3], ba);
            vb.x = fmaf(a1[0], mm[0], bb); vb.y = fmaf(a1[1], mm[1], bb);
            vb.z = fmaf(a1[2], mm[2], bb); vb.w = fmaf(a1[3], mm[3], bb);
            *reinterpret_cast<float4*>(out + ((size_t)b * 64 + oa) * HW_ + bhw0) = va;
            *reinterpret_cast<float4*>(out + ((size_t)b * 64 + ob2) * HW_ + bhw0) = vb;
        }
    }
}

// ---------------------------------------------------------------------------
extern "C" void kernel_launch(void* const* d_in, const int* in_sizes, int n_in,
                              void* d_out, int out_size)
{
    const float* x      = (const float*)d_in[0];
    const float* weight = (const float*)d_in[1];
    const float* bias   = (const float*)d_in[2];
    const float* ow     = (const float*)d_in[3];
    const float* ob     = (const float*)d_in[4];
    const float* mw     = (const float*)d_in[5];
    const float* mb     = (const float*)d_in[6];
    float* out = (float*)d_out;

    const size_t sm_off = (size_t)(32 * 324 + 32 * 9 * 28) * sizeof(float); // 73728
    cudaFuncSetAttribute(k_offmod, cudaFuncAttributeMaxDynamicSharedMemorySize,
                         (int)sm_off);

    k_wprep<<<(9 * 64 * 64 + 255) / 256, 256>>>(weight);

    dim3 grd_off(W_ / 16, H_ / 16, B_);
    k_offmod<<<grd_off, 256, sm_off>>>(x, ow, ob, mw, mb);

    dim3 grd_main(W_ / 32, H_ / 8, B_);
    k_main<<<grd_main, 256>>>(x, bias, out);
}